// round 7
// baseline (speedup 1.0000x reference)
#include <cuda_runtime.h>
#include <cuda_fp16.h>
#include <math.h>
#include <cstdint>

// ---------------------------------------------------------------------------
// Scratch
// ---------------------------------------------------------------------------
#define C0_OFF   0u
#define C1_OFF   6291456u
#define C2_OFF   7864320u
#define C3_OFF   8257536u
#define HI_OFF   8355840u
#define HJ_OFF   9404416u
#define SP_OFF   10452992u                // 2048*256 floats
#define WP_OFF   11501568u                // fp16 blob: 24*8192 ushorts = 384KB
#define SCRATCH_TOTAL 11698176u

__device__ float g_scratch[SCRATCH_TOTAL];

// ---------------------------------------------------------------------------
// Helpers
// ---------------------------------------------------------------------------
__device__ __forceinline__ uint32_t smem_u32(const void* p) {
    uint32_t a;
    asm("{ .reg .u64 t; cvta.to.shared.u64 t, %1; cvt.u32.u64 %0, t; }" : "=r"(a) : "l"(p));
    return a;
}

__device__ __forceinline__ void mma_f16(float& d0, float& d1, float& d2, float& d3,
                                        uint32_t a0, uint32_t a1, uint32_t a2, uint32_t a3,
                                        uint32_t b0, uint32_t b1) {
    asm volatile(
        "mma.sync.aligned.m16n8k16.row.col.f32.f16.f16.f32 "
        "{%0,%1,%2,%3},{%4,%5,%6,%7},{%8,%9},{%0,%1,%2,%3};"
        : "+f"(d0), "+f"(d1), "+f"(d2), "+f"(d3)
        : "r"(a0), "r"(a1), "r"(a2), "r"(a3), "r"(b0), "r"(b1));
}

// pack: low half = f16(v0), high half = f16(v1)
__device__ __forceinline__ uint32_t packh(float v0, float v1) {
    uint32_t r;
    asm("cvt.rn.f16x2.f32 %0, %1, %2;" : "=r"(r) : "f"(v1), "f"(v0));
    return r;
}

#define CP_ASYNC16(dst, src) \
    asm volatile("cp.async.cg.shared.global [%0], [%1], 16;" :: "r"(dst), "l"(src) : "memory")
#define CP_COMMIT() asm volatile("cp.async.commit_group;" ::: "memory")

// ---------------------------------------------------------------------------
// Conv + BN + ReLU (R3 proven version)
// ---------------------------------------------------------------------------
template<int CIN, int CHUNK>
__global__ void __launch_bounds__(192) conv_bn_relu_kernel(
    const float* __restrict__ in, const float* __restrict__ w,
    const float* __restrict__ bns, const float* __restrict__ bnb,
    float* __restrict__ out, int Hin, int Hout, int tps)
{
    __shared__ float in_s[CHUNK * 289];
    __shared__ float w_s[9 * CHUNK * 24];

    int t   = threadIdx.x;
    int co  = t % 24;
    int ohl = t / 24;
    int tiles = tps * tps;
    int n  = blockIdx.x / tiles;
    int tl = blockIdx.x % tiles;
    int oh0 = (tl / tps) * 8;
    int ow0 = (tl % tps) * 8;

    float acc[8];
#pragma unroll
    for (int i = 0; i < 8; i++) acc[i] = 0.f;

    for (int cc = 0; cc < CIN; cc += CHUNK) {
        __syncthreads();
        for (int l = t; l < CHUNK * 289; l += 192) {
            int ci  = l / 289;
            int rem = l % 289;
            int r = rem / 17, c = rem % 17;
            int ih = oh0 * 2 - 1 + r;
            int iw = ow0 * 2 - 1 + c;
            float v = 0.f;
            if (ih >= 0 && ih < Hin && iw >= 0 && iw < Hin)
                v = in[((n * CIN + cc + ci) * Hin + ih) * Hin + iw];
            in_s[l] = v;
        }
        for (int l = t; l < 9 * CHUNK * 24; l += 192) {
            int kk  = l / (CHUNK * 24);
            int rem = l % (CHUNK * 24);
            int ci = rem / 24, c2 = rem % 24;
            w_s[l] = w[(kk * CIN + cc + ci) * 24 + c2];
        }
        __syncthreads();

#pragma unroll
        for (int kh = 0; kh < 3; kh++)
#pragma unroll
            for (int kw = 0; kw < 3; kw++)
                for (int ci = 0; ci < CHUNK; ci++) {
                    float wv = w_s[(kh * 3 + kw) * CHUNK * 24 + ci * 24 + co];
                    const float* ir = &in_s[ci * 289 + (ohl * 2 + kh) * 17 + kw];
#pragma unroll
                    for (int o = 0; o < 8; o++)
                        acc[o] += wv * ir[o * 2];
                }
    }

    float sc = bns[co], bb = bnb[co];
#pragma unroll
    for (int o = 0; o < 8; o++) {
        float v = fmaxf(acc[o] * sc + bb, 0.f);
        out[((n * 24 + co) * Hout + oh0 + ohl) * Hout + ow0 + o] = v;
    }
}

// ---------------------------------------------------------------------------
// g layer 1: grid 256 (4 blocks per n, 16 p rows each)
// ---------------------------------------------------------------------------
__global__ void __launch_bounds__(256) g1_kernel(
    const float* __restrict__ c3, const float* __restrict__ qst,
    const float* __restrict__ gw1, const float* __restrict__ gb1,
    float* __restrict__ hi, float* __restrict__ hj)
{
    __shared__ float xs[64 * 26];
    __shared__ float qs[128];
    int n = blockIdx.x >> 2, pg = blockIdx.x & 3;
    int t = threadIdx.x;

    for (int l = t; l < 64 * 26; l += 256) {
        int p = l / 26, c = l % 26;
        int h = p >> 3, w = p & 7;
        float v;
        if (c < 24)       v = c3[((n * 24 + c) * 8 + h) * 8 + w];
        else if (c == 24) v = -1.f + (2.f / 7.f) * (float)w;
        else              v = -1.f + (2.f / 7.f) * (float)h;
        xs[l] = v;
    }
    if (t < 128) qs[t] = qst[n * 128 + t];
    __syncthreads();

    int o = t;
    float wa[26], wb[26];
#pragma unroll
    for (int c = 0; c < 26; c++) {
        wa[c] = gw1[c * 256 + o];
        wb[c] = gw1[(26 + c) * 256 + o];
    }
    float hq = gb1[o];
    for (int k = 0; k < 128; k++) hq += qs[k] * gw1[(52 + k) * 256 + o];

    for (int p = pg * 16; p < pg * 16 + 16; p++) {
        float ai = hq, bj = 0.f;
#pragma unroll
        for (int c = 0; c < 26; c++) {
            float x = xs[p * 26 + c];
            ai += x * wa[c];
            bj += x * wb[c];
        }
        hi[(n * 64 + p) * 256 + o] = ai;
        hj[(n * 64 + p) * 256 + o] = bj;
    }
}

// ---------------------------------------------------------------------------
// Weight prep: W[k][n] fp32 -> fragment-ordered fp16 blob (unchanged)
// ---------------------------------------------------------------------------
__global__ void __launch_bounds__(256) prep_w_kernel(
    const float* __restrict__ w2, const float* __restrict__ w3,
    const float* __restrict__ w4, unsigned short* __restrict__ blob)
{
    int idx = blockIdx.x * 256 + threadIdx.x;      // 0..196607
    int l = idx >> 16;
    int rem = idx & 65535;
    int k = rem >> 8, n = rem & 255;
    const float* W = (l == 0) ? w2 : ((l == 1) ? w3 : w4);
    __half wh = __float2half(W[k * 256 + n]);

    int c   = k >> 5;
    int k2c = (k >> 1) & 15;
    int s   = k2c >> 3;
    int wi  = k2c & 7;
    int pos = s * 8 + ((wi < 4) ? (wi * 2) : ((wi - 4) * 2 + 1));
    int gc  = l * 8 + c;
    blob[(size_t)gc * 8192 + (n * 16 + pos) * 2 + (k & 1)] = *(unsigned short*)&wh;
}

// ---------------------------------------------------------------------------
// fp16 mma relation MLP. Block = 128 pairs (2 i x 64 j), 256 threads = 8 warps.
// Warp tile = 32 M x 128 N: wm 0..3 (32-row strips), wn 0..1 (128-col halves).
// SMEM words: A[0,16896) rows 128 x stride 132 (fp16x2)
//             WB0[16896,22016) WB1[22016,27136) (20 words per n)
//             bias[27136,27904) red[27904,28928)  -> 115712 bytes
// One __syncthreads per chunk: wait -> sync -> issue(next) -> compute.
// ---------------------------------------------------------------------------
extern __shared__ uint32_t smw[];

__device__ __forceinline__ void issue_chunk(const char* __restrict__ blob,
                                            uint32_t wsm, int gc, int tid)
{
    const char* src = blob + (size_t)gc * 16384;
#pragma unroll
    for (int r = 0; r < 4; r++) {
        int op = r * 256 + tid;          // 0..1023
        int n = op >> 2, v = op & 3;
        uint32_t dst = wsm + (uint32_t)(n * 80 + v * 16);
        CP_ASYNC16(dst, src + n * 64 + v * 16);
    }
    CP_COMMIT();
}

__global__ void __launch_bounds__(256) rn_g_mma(
    const float* __restrict__ hi, const float* __restrict__ hj,
    const unsigned short* __restrict__ wblob,
    const float* __restrict__ b2, const float* __restrict__ b3,
    const float* __restrict__ b4, float* __restrict__ spart)
{
    const char* blob = (const char*)wblob;
    int tid = threadIdx.x;
    int wid = tid >> 5, lane = tid & 31;
    int g = lane >> 2, t = lane & 3;
    int wm = wid & 3, wn = wid >> 2;

    float* biasf = (float*)&smw[27136];
    float* red   = (float*)&smw[27904];
    uint32_t sb = smem_u32(smw);
    uint32_t wsm0 = sb + 67584u;           // WB0 bytes
    uint32_t wsm1 = sb + 88064u;           // WB1

    biasf[tid]       = b2[tid];
    biasf[256 + tid] = b3[tid];
    biasf[512 + tid] = b4[tid];

    issue_chunk(blob, wsm0, 0, tid);

    // ---- L0: A = relu(hi_i + hj_j) as fp16x2; m = 0..127
    int nb = blockIdx.x >> 5;
    int ip = blockIdx.x & 31;
    {
        int m = tid >> 1, q = tid & 1;
        const float* hir = hi + (size_t)(nb * 64 + ip * 2 + (m >> 6)) * 256 + q * 128;
        const float* hjr = hj + (size_t)(nb * 64 + (m & 63)) * 256 + q * 128;
        int base = m * 132 + q * 64;
#pragma unroll 8
        for (int w = 0; w < 64; w++) {
            float2 a = *(const float2*)(hir + 2 * w);
            float2 b = *(const float2*)(hjr + 2 * w);
            smw[base + w] = packh(fmaxf(a.x + b.x, 0.f), fmaxf(a.y + b.y, 0.f));
        }
    }

    float acc[2][16][4];
    int rb0 = (wm * 32 + g) * 132;          // strip rows [wm*32, +16)
    int rb1 = rb0 + 16 * 132;               // strip rows [wm*32+16, +16)

#pragma unroll 1
    for (int l = 0; l < 3; l++) {
#pragma unroll
        for (int mt = 0; mt < 2; mt++)
#pragma unroll
            for (int nt = 0; nt < 16; nt++)
#pragma unroll
                for (int q = 0; q < 4; q++) acc[mt][nt][q] = 0.f;

#pragma unroll 1
        for (int c = 0; c < 8; c++) {
            int gc = l * 8 + c;
            asm volatile("cp.async.wait_group 0;" ::: "memory");
            __syncthreads();
            if (gc < 23)
                issue_chunk(blob, ((gc + 1) & 1) ? wsm1 : wsm0, gc + 1, tid);

            uint32_t wb = 16896u + (uint32_t)(gc & 1) * 5120u;
#pragma unroll
            for (int s = 0; s < 2; s++) {
                int ks8 = (c * 2 + s) * 8;
                uint32_t a00 = smw[rb0 + ks8 + t];
                uint32_t a01 = smw[rb0 + 1056 + ks8 + t];
                uint32_t a02 = smw[rb0 + ks8 + t + 4];
                uint32_t a03 = smw[rb0 + 1056 + ks8 + t + 4];
                uint32_t a10 = smw[rb1 + ks8 + t];
                uint32_t a11 = smw[rb1 + 1056 + ks8 + t];
                uint32_t a12 = smw[rb1 + ks8 + t + 4];
                uint32_t a13 = smw[rb1 + 1056 + ks8 + t + 4];
#pragma unroll
                for (int nt = 0; nt < 16; nt++) {
                    uint32_t nw = (uint32_t)((wn * 128 + nt * 8 + g) * 20 + s * 8 + 2 * t);
                    uint2 bh = *(const uint2*)&smw[wb + nw];
                    mma_f16(acc[0][nt][0], acc[0][nt][1], acc[0][nt][2], acc[0][nt][3],
                            a00, a01, a02, a03, bh.x, bh.y);
                    mma_f16(acc[1][nt][0], acc[1][nt][1], acc[1][nt][2], acc[1][nt][3],
                            a10, a11, a12, a13, bh.x, bh.y);
                }
            }
        }
        __syncthreads();   // all MMA reads of A done before epilogue overwrites A

        if (l < 2) {
#pragma unroll
            for (int mt = 0; mt < 2; mt++)
#pragma unroll
                for (int nt = 0; nt < 16; nt++) {
                    int n0 = wn * 128 + nt * 8 + 2 * t;
                    float2 bv = *(const float2*)&biasf[l * 256 + n0];
                    int nh = n0 >> 1;
                    int rbase = (wm * 32 + mt * 16 + g) * 132;
                    smw[rbase + nh] =
                        packh(fmaxf(acc[mt][nt][0] + bv.x, 0.f),
                              fmaxf(acc[mt][nt][1] + bv.y, 0.f));
                    smw[rbase + 1056 + nh] =
                        packh(fmaxf(acc[mt][nt][2] + bv.x, 0.f),
                              fmaxf(acc[mt][nt][3] + bv.y, 0.f));
                }
        } else {
#pragma unroll
            for (int nt = 0; nt < 16; nt++) {
                int n0 = wn * 128 + nt * 8 + 2 * t;
                float2 bv = *(const float2*)&biasf[512 + n0];
                float cs0 = fmaxf(acc[0][nt][0] + bv.x, 0.f) + fmaxf(acc[0][nt][2] + bv.x, 0.f)
                          + fmaxf(acc[1][nt][0] + bv.x, 0.f) + fmaxf(acc[1][nt][2] + bv.x, 0.f);
                float cs1 = fmaxf(acc[0][nt][1] + bv.y, 0.f) + fmaxf(acc[0][nt][3] + bv.y, 0.f)
                          + fmaxf(acc[1][nt][1] + bv.y, 0.f) + fmaxf(acc[1][nt][3] + bv.y, 0.f);
#pragma unroll
                for (int off = 16; off >= 4; off >>= 1) {
                    cs0 += __shfl_xor_sync(0xffffffffu, cs0, off);
                    cs1 += __shfl_xor_sync(0xffffffffu, cs1, off);
                }
                if (g == 0) {
                    red[wm * 256 + n0] = cs0;
                    red[wm * 256 + n0 + 1] = cs1;
                }
            }
            __syncthreads();
            float s = red[tid] + red[256 + tid] + red[512 + tid] + red[768 + tid];
            spart[(size_t)blockIdx.x * 256 + tid] = s;
        }
    }
}

// ---------------------------------------------------------------------------
// Reduce 32 partials per n, f-MLP + classifier + log_softmax
// ---------------------------------------------------------------------------
__global__ void __launch_bounds__(256) f_kernel(
    const float* __restrict__ spart,
    const float* __restrict__ fw1, const float* __restrict__ fb1,
    const float* __restrict__ fw2, const float* __restrict__ fb2,
    const float* __restrict__ cw,  const float* __restrict__ cb,
    float* __restrict__ out)
{
    __shared__ float a[256], b[256];
    int n = blockIdx.x, t = threadIdx.x;

    const float* sp = spart + (size_t)(n * 32) * 256 + t;
    float v = 0.f;
    for (int i = 0; i < 32; i++) v += sp[i * 256];
    a[t] = v;
    __syncthreads();

    float acc = fb1[t];
    for (int k = 0; k < 256; k++) acc += a[k] * fw1[k * 256 + t];
    acc = fmaxf(acc, 0.f);
    b[t] = acc;
    __syncthreads();

    acc = fb2[t];
    for (int k = 0; k < 256; k++) acc += b[k] * fw2[k * 256 + t];
    acc = fmaxf(acc, 0.f);
    a[t] = acc;
    __syncthreads();

    if (t < 32) {
        float lg = cb[t];
        for (int k = 0; k < 256; k++) lg += a[k] * cw[k * 32 + t];
        float mx = lg;
#pragma unroll
        for (int off = 16; off; off >>= 1)
            mx = fmaxf(mx, __shfl_xor_sync(0xffffffffu, mx, off));
        float e = expf(lg - mx);
        float se = e;
#pragma unroll
        for (int off = 16; off; off >>= 1)
            se += __shfl_xor_sync(0xffffffffu, se, off);
        out[(n << 5) + t] = lg - mx - logf(se);
    }
}

// ---------------------------------------------------------------------------
// Launch
// ---------------------------------------------------------------------------
extern "C" void kernel_launch(void* const* d_in, const int* in_sizes, int n_in,
                              void* d_out, int out_size)
{
    const float* img  = (const float*)d_in[0];
    const float* qst  = (const float*)d_in[1];
    const float* cw0  = (const float*)d_in[2];
    const float* cw1  = (const float*)d_in[3];
    const float* cw2  = (const float*)d_in[4];
    const float* cw3  = (const float*)d_in[5];
    const float* bs0  = (const float*)d_in[6];
    const float* bb0  = (const float*)d_in[7];
    const float* bs1  = (const float*)d_in[8];
    const float* bb1  = (const float*)d_in[9];
    const float* bs2  = (const float*)d_in[10];
    const float* bb2  = (const float*)d_in[11];
    const float* bs3  = (const float*)d_in[12];
    const float* bb3  = (const float*)d_in[13];
    const float* gw1  = (const float*)d_in[14];
    const float* gb1  = (const float*)d_in[15];
    const float* gw2  = (const float*)d_in[16];
    const float* gb2  = (const float*)d_in[17];
    const float* gw3  = (const float*)d_in[18];
    const float* gb3  = (const float*)d_in[19];
    const float* gw4  = (const float*)d_in[20];
    const float* gb4  = (const float*)d_in[21];
    const float* fw1  = (const float*)d_in[22];
    const float* fb1  = (const float*)d_in[23];
    const float* fw2  = (const float*)d_in[24];
    const float* fb2  = (const float*)d_in[25];
    const float* clw  = (const float*)d_in[26];
    const float* clb  = (const float*)d_in[27];
    float* out = (float*)d_out;

    void* base_v = nullptr;
    cudaGetSymbolAddress(&base_v, g_scratch);
    float* base = (float*)base_v;
    float* c0 = base + C0_OFF;
    float* c1 = base + C1_OFF;
    float* c2 = base + C2_OFF;
    float* c3 = base + C3_OFF;
    float* hi = base + HI_OFF;
    float* hj = base + HJ_OFF;
    float* sp = base + SP_OFF;
    unsigned short* wp = (unsigned short*)(base + WP_OFF);

    cudaFuncSetAttribute(rn_g_mma, cudaFuncAttributeMaxDynamicSharedMemorySize, 115712);

    prep_w_kernel<<<768, 256>>>(gw2, gw3, gw4, wp);

    conv_bn_relu_kernel<3, 3><<<4096, 192>>>(img, cw0, bs0, bb0, c0, 128, 64, 8);
    conv_bn_relu_kernel<24, 12><<<1024, 192>>>(c0, cw1, bs1, bb1, c1, 64, 32, 4);
    conv_bn_relu_kernel<24, 12><<<256, 192>>>(c1, cw2, bs2, bb2, c2, 32, 16, 2);
    conv_bn_relu_kernel<24, 12><<<64, 192>>>(c2, cw3, bs3, bb3, c3, 16, 8, 1);

    g1_kernel<<<256, 256>>>(c3, qst, gw1, gb1, hi, hj);

    rn_g_mma<<<2048, 256, 115712>>>(hi, hj, wp, gb2, gb3, gb4, sp);

    f_kernel<<<64, 256>>>(sp, fw1, fb1, fw2, fb2, clw, clb, out);
}

// round 9
// speedup vs baseline: 1.0260x; 1.0260x over previous
#include <cuda_runtime.h>
#include <cuda_fp16.h>
#include <math.h>
#include <cstdint>

// ---------------------------------------------------------------------------
// Scratch
// ---------------------------------------------------------------------------
#define C0_OFF   0u
#define C1_OFF   6291456u
#define C2_OFF   7864320u
#define C3_OFF   8257536u
#define HI_OFF   8355840u
#define HJ_OFF   9404416u
#define SP_OFF   10452992u                // 4096*256 floats
#define WP_OFF   11501568u                // fp16 blob: 24*8192 ushorts = 384KB
#define SCRATCH_TOTAL 11698176u

__device__ float g_scratch[SCRATCH_TOTAL];

// ---------------------------------------------------------------------------
// Helpers
// ---------------------------------------------------------------------------
__device__ __forceinline__ uint32_t smem_u32(const void* p) {
    uint32_t a;
    asm("{ .reg .u64 t; cvta.to.shared.u64 t, %1; cvt.u32.u64 %0, t; }" : "=r"(a) : "l"(p));
    return a;
}

__device__ __forceinline__ void mma_f16(float& d0, float& d1, float& d2, float& d3,
                                        uint32_t a0, uint32_t a1, uint32_t a2, uint32_t a3,
                                        uint32_t b0, uint32_t b1) {
    asm volatile(
        "mma.sync.aligned.m16n8k16.row.col.f32.f16.f16.f32 "
        "{%0,%1,%2,%3},{%4,%5,%6,%7},{%8,%9},{%0,%1,%2,%3};"
        : "+f"(d0), "+f"(d1), "+f"(d2), "+f"(d3)
        : "r"(a0), "r"(a1), "r"(a2), "r"(a3), "r"(b0), "r"(b1));
}

// pack: low half = f16(v0), high half = f16(v1)
__device__ __forceinline__ uint32_t packh(float v0, float v1) {
    uint32_t r;
    asm("cvt.rn.f16x2.f32 %0, %1, %2;" : "=r"(r) : "f"(v1), "f"(v0));
    return r;
}

#define CP_ASYNC16(dst, src) \
    asm volatile("cp.async.cg.shared.global [%0], [%1], 16;" :: "r"(dst), "l"(src) : "memory")
#define CP_COMMIT() asm volatile("cp.async.commit_group;" ::: "memory")

// ---------------------------------------------------------------------------
// Slab-parallel Conv + BN + ReLU (stride 2, pad 1, 3x3).
// Block = (n, RPB-row slab of the WxW output). Threads = 24co x RPB x (W/CPT).
// Each thread computes CPT adjacent output cols for one (co, row).
// Weights fully smem-resident; input reads are warp-broadcasts.
// ---------------------------------------------------------------------------
template<int CIN, int W, int RPB, int CPT>
__global__ void __launch_bounds__(24 * RPB * (W / CPT)) conv_slab_kernel(
    const float* __restrict__ in, const float* __restrict__ w,
    const float* __restrict__ bns, const float* __restrict__ bnb,
    float* __restrict__ out, int Hin)
{
    constexpr int NT = 24 * RPB * (W / CPT);
    constexpr int R  = 2 * RPB + 1;
    constexpr int C  = 2 * W + 1;
    constexpr int Cp = 2 * W + 2;

    __shared__ float in_s[CIN * R * Cp];
    __shared__ float w_s[9 * CIN * 24];

    int t = threadIdx.x;
    constexpr int SLABS = W / RPB;
    int n    = blockIdx.x / SLABS;
    int slab = blockIdx.x % SLABS;
    int co   = t % 24;
    int rest = t / 24;
    int tcol = rest % (W / CPT);
    int orow = rest / (W / CPT);          // 0..RPB-1

    for (int l = t; l < 9 * CIN * 24; l += NT) w_s[l] = w[l];

    int ih0 = slab * RPB * 2 - 1;
    for (int l = t; l < CIN * R * C; l += NT) {
        int ci  = l / (R * C);
        int rem = l % (R * C);
        int r = rem / C, c = rem % C;
        int ih = ih0 + r, iw = c - 1;
        float v = 0.f;
        if (ih >= 0 && ih < Hin && iw >= 0 && iw < Hin)
            v = in[((n * CIN + ci) * Hin + ih) * Hin + iw];
        in_s[ci * (R * Cp) + r * Cp + c] = v;
    }
    __syncthreads();

    float acc[CPT];
#pragma unroll
    for (int o = 0; o < CPT; o++) acc[o] = 0.f;

#pragma unroll 2
    for (int ci = 0; ci < CIN; ci++) {
        float wr[9];
#pragma unroll
        for (int k = 0; k < 9; k++) wr[k] = w_s[k * (CIN * 24) + ci * 24 + co];
#pragma unroll
        for (int kh = 0; kh < 3; kh++) {
            const float* row = &in_s[ci * (R * Cp) + (orow * 2 + kh) * Cp + tcol * CPT * 2];
#pragma unroll
            for (int o = 0; o < CPT; o++) {
                acc[o] += wr[kh * 3 + 0] * row[2 * o];
                acc[o] += wr[kh * 3 + 1] * row[2 * o + 1];
                acc[o] += wr[kh * 3 + 2] * row[2 * o + 2];
            }
        }
    }

    float sc = bns[co], bb = bnb[co];
#pragma unroll
    for (int o = 0; o < CPT; o++) {
        float v = fmaxf(acc[o] * sc + bb, 0.f);
        out[((n * 24 + co) * W + slab * RPB + orow) * W + tcol * CPT + o] = v;
    }
}

// ---------------------------------------------------------------------------
// g layer 1: grid 256 (4 blocks per n, 16 p rows each)
// ---------------------------------------------------------------------------
__global__ void __launch_bounds__(256) g1_kernel(
    const float* __restrict__ c3, const float* __restrict__ qst,
    const float* __restrict__ gw1, const float* __restrict__ gb1,
    float* __restrict__ hi, float* __restrict__ hj)
{
    __shared__ float xs[64 * 26];
    __shared__ float qs[128];
    int n = blockIdx.x >> 2, pg = blockIdx.x & 3;
    int t = threadIdx.x;

    for (int l = t; l < 64 * 26; l += 256) {
        int p = l / 26, c = l % 26;
        int h = p >> 3, w = p & 7;
        float v;
        if (c < 24)       v = c3[((n * 24 + c) * 8 + h) * 8 + w];
        else if (c == 24) v = -1.f + (2.f / 7.f) * (float)w;
        else              v = -1.f + (2.f / 7.f) * (float)h;
        xs[l] = v;
    }
    if (t < 128) qs[t] = qst[n * 128 + t];
    __syncthreads();

    int o = t;
    float wa[26], wb[26];
#pragma unroll
    for (int c = 0; c < 26; c++) {
        wa[c] = gw1[c * 256 + o];
        wb[c] = gw1[(26 + c) * 256 + o];
    }
    float hq = gb1[o];
    for (int k = 0; k < 128; k++) hq += qs[k] * gw1[(52 + k) * 256 + o];

    for (int p = pg * 16; p < pg * 16 + 16; p++) {
        float ai = hq, bj = 0.f;
#pragma unroll
        for (int c = 0; c < 26; c++) {
            float x = xs[p * 26 + c];
            ai += x * wa[c];
            bj += x * wb[c];
        }
        hi[(n * 64 + p) * 256 + o] = ai;
        hj[(n * 64 + p) * 256 + o] = bj;
    }
}

// ---------------------------------------------------------------------------
// Weight prep: W[k][n] fp32 -> fragment-ordered fp16 blob (unchanged)
// ---------------------------------------------------------------------------
__global__ void __launch_bounds__(256) prep_w_kernel(
    const float* __restrict__ w2, const float* __restrict__ w3,
    const float* __restrict__ w4, unsigned short* __restrict__ blob)
{
    int idx = blockIdx.x * 256 + threadIdx.x;      // 0..196607
    int l = idx >> 16;
    int rem = idx & 65535;
    int k = rem >> 8, n = rem & 255;
    const float* W = (l == 0) ? w2 : ((l == 1) ? w3 : w4);
    __half wh = __float2half(W[k * 256 + n]);

    int c   = k >> 5;
    int k2c = (k >> 1) & 15;
    int s   = k2c >> 3;
    int wi  = k2c & 7;
    int pos = s * 8 + ((wi < 4) ? (wi * 2) : ((wi - 4) * 2 + 1));
    int gc  = l * 8 + c;
    blob[(size_t)gc * 8192 + (n * 16 + pos) * 2 + (k & 1)] = *(unsigned short*)&wh;
}

// ---------------------------------------------------------------------------
// fp16 mma relation MLP (R6 proven version).
// Block = 64 pairs (1 i x 64 j), 256 threads = 8 warps.
// Warp tile = 32 M x 64 N: wm 0..1 (32-row strips), wn 0..3 (64-col quarters).
// SMEM words: A[0,8448) rows 64 x stride 132 (fp16x2)
//             WB0[8448,13568) WB1[13568,18688) (20 words per n)
//             bias[18688,19456) red[19456,19968)  -> 79872 bytes
// ---------------------------------------------------------------------------
extern __shared__ uint32_t smw[];

__device__ __forceinline__ void issue_chunk(const char* __restrict__ blob,
                                            uint32_t wsm, int gc, int tid)
{
    const char* src = blob + (size_t)gc * 16384;
#pragma unroll
    for (int r = 0; r < 4; r++) {
        int op = r * 256 + tid;          // 0..1023
        int n = op >> 2, v = op & 3;
        uint32_t dst = wsm + (uint32_t)(n * 80 + v * 16);
        CP_ASYNC16(dst, src + n * 64 + v * 16);
    }
    CP_COMMIT();
}

__global__ void __launch_bounds__(256) rn_g_mma(
    const float* __restrict__ hi, const float* __restrict__ hj,
    const unsigned short* __restrict__ wblob,
    const float* __restrict__ b2, const float* __restrict__ b3,
    const float* __restrict__ b4, float* __restrict__ spart)
{
    const char* blob = (const char*)wblob;
    int tid = threadIdx.x;
    int wid = tid >> 5, lane = tid & 31;
    int g = lane >> 2, t = lane & 3;
    int wm = wid & 1, wn = wid >> 1;

    float* biasf = (float*)&smw[18688];
    float* red   = (float*)&smw[19456];
    uint32_t sb = smem_u32(smw);
    uint32_t wsm0 = sb + 33792u;
    uint32_t wsm1 = sb + 54272u;

    biasf[tid]       = b2[tid];
    biasf[256 + tid] = b3[tid];
    biasf[512 + tid] = b4[tid];

    issue_chunk(blob, wsm0, 0, tid);

    // ---- L0: A = relu(hi_i + hj_j) as fp16x2
    int nb = blockIdx.x >> 6;
    int ii = blockIdx.x & 63;
    {
        int m = tid >> 2, q = tid & 3;
        const float* hir = hi + (size_t)(nb * 64 + ii) * 256 + q * 64;
        const float* hjr = hj + (size_t)(nb * 64 + m) * 256 + q * 64;
        int base = m * 132 + q * 32;
#pragma unroll 8
        for (int w = 0; w < 32; w++) {
            float2 a = *(const float2*)(hir + 2 * w);
            float2 b = *(const float2*)(hjr + 2 * w);
            smw[base + w] = packh(fmaxf(a.x + b.x, 0.f), fmaxf(a.y + b.y, 0.f));
        }
    }

    float acc[2][8][4];
    int rb0 = (wm * 32 + g) * 132;          // strip rows [wm*32, +16)
    int rb1 = (wm * 32 + 16 + g) * 132;     // strip rows [wm*32+16, +16)

#pragma unroll 1
    for (int l = 0; l < 3; l++) {
#pragma unroll
        for (int mt = 0; mt < 2; mt++)
#pragma unroll
            for (int nt = 0; nt < 8; nt++)
#pragma unroll
                for (int q = 0; q < 4; q++) acc[mt][nt][q] = 0.f;

#pragma unroll 1
        for (int c = 0; c < 8; c++) {
            int gc = l * 8 + c;
            asm volatile("cp.async.wait_group 0;" ::: "memory");
            __syncthreads();
            if (gc < 23)
                issue_chunk(blob, ((gc + 1) & 1) ? wsm1 : wsm0, gc + 1, tid);

            uint32_t wb = 8448u + (uint32_t)(gc & 1) * 5120u;
#pragma unroll
            for (int s = 0; s < 2; s++) {
                int ks8 = (c * 2 + s) * 8;
                uint32_t a00 = smw[rb0 + ks8 + t];
                uint32_t a01 = smw[rb0 + 1056 + ks8 + t];
                uint32_t a02 = smw[rb0 + ks8 + t + 4];
                uint32_t a03 = smw[rb0 + 1056 + ks8 + t + 4];
                uint32_t a10 = smw[rb1 + ks8 + t];
                uint32_t a11 = smw[rb1 + 1056 + ks8 + t];
                uint32_t a12 = smw[rb1 + ks8 + t + 4];
                uint32_t a13 = smw[rb1 + 1056 + ks8 + t + 4];
#pragma unroll
                for (int nt = 0; nt < 8; nt++) {
                    uint32_t nw = (uint32_t)((wn * 64 + nt * 8 + g) * 20 + s * 8 + 2 * t);
                    uint2 bh = *(const uint2*)&smw[wb + nw];
                    mma_f16(acc[0][nt][0], acc[0][nt][1], acc[0][nt][2], acc[0][nt][3],
                            a00, a01, a02, a03, bh.x, bh.y);
                    mma_f16(acc[1][nt][0], acc[1][nt][1], acc[1][nt][2], acc[1][nt][3],
                            a10, a11, a12, a13, bh.x, bh.y);
                }
            }
        }
        __syncthreads();   // all MMA reads of A done before epilogue overwrites A

        if (l < 2) {
#pragma unroll
            for (int mt = 0; mt < 2; mt++)
#pragma unroll
                for (int nt = 0; nt < 8; nt++) {
                    int n0 = wn * 64 + nt * 8 + 2 * t;
                    float2 bv = *(const float2*)&biasf[l * 256 + n0];
                    int nh = n0 >> 1;
                    int rbase = (wm * 32 + mt * 16 + g) * 132;
                    smw[rbase + nh] =
                        packh(fmaxf(acc[mt][nt][0] + bv.x, 0.f),
                              fmaxf(acc[mt][nt][1] + bv.y, 0.f));
                    smw[rbase + 1056 + nh] =
                        packh(fmaxf(acc[mt][nt][2] + bv.x, 0.f),
                              fmaxf(acc[mt][nt][3] + bv.y, 0.f));
                }
        } else {
#pragma unroll
            for (int nt = 0; nt < 8; nt++) {
                int n0 = wn * 64 + nt * 8 + 2 * t;
                float2 bv = *(const float2*)&biasf[512 + n0];
                float cs0 = fmaxf(acc[0][nt][0] + bv.x, 0.f) + fmaxf(acc[0][nt][2] + bv.x, 0.f)
                          + fmaxf(acc[1][nt][0] + bv.x, 0.f) + fmaxf(acc[1][nt][2] + bv.x, 0.f);
                float cs1 = fmaxf(acc[0][nt][1] + bv.y, 0.f) + fmaxf(acc[0][nt][3] + bv.y, 0.f)
                          + fmaxf(acc[1][nt][1] + bv.y, 0.f) + fmaxf(acc[1][nt][3] + bv.y, 0.f);
#pragma unroll
                for (int off = 16; off >= 4; off >>= 1) {
                    cs0 += __shfl_xor_sync(0xffffffffu, cs0, off);
                    cs1 += __shfl_xor_sync(0xffffffffu, cs1, off);
                }
                if (g == 0) {
                    red[wm * 256 + n0] = cs0;
                    red[wm * 256 + n0 + 1] = cs1;
                }
            }
            __syncthreads();
            float s = red[tid] + red[256 + tid];
            spart[(size_t)blockIdx.x * 256 + tid] = s;
        }
    }
}

// ---------------------------------------------------------------------------
// Reduce 64 partials per n, f-MLP + classifier + log_softmax
// ---------------------------------------------------------------------------
__global__ void __launch_bounds__(256) f_kernel(
    const float* __restrict__ spart,
    const float* __restrict__ fw1, const float* __restrict__ fb1,
    const float* __restrict__ fw2, const float* __restrict__ fb2,
    const float* __restrict__ cw,  const float* __restrict__ cb,
    float* __restrict__ out)
{
    __shared__ float a[256], b[256];
    int n = blockIdx.x, t = threadIdx.x;

    const float* sp = spart + (size_t)(n * 64) * 256 + t;
    float v = 0.f;
    for (int i = 0; i < 64; i++) v += sp[i * 256];
    a[t] = v;
    __syncthreads();

    float acc = fb1[t];
    for (int k = 0; k < 256; k++) acc += a[k] * fw1[k * 256 + t];
    acc = fmaxf(acc, 0.f);
    b[t] = acc;
    __syncthreads();

    acc = fb2[t];
    for (int k = 0; k < 256; k++) acc += b[k] * fw2[k * 256 + t];
    acc = fmaxf(acc, 0.f);
    a[t] = acc;
    __syncthreads();

    if (t < 32) {
        float lg = cb[t];
        for (int k = 0; k < 256; k++) lg += a[k] * cw[k * 32 + t];
        float mx = lg;
#pragma unroll
        for (int off = 16; off; off >>= 1)
            mx = fmaxf(mx, __shfl_xor_sync(0xffffffffu, mx, off));
        float e = expf(lg - mx);
        float se = e;
#pragma unroll
        for (int off = 16; off; off >>= 1)
            se += __shfl_xor_sync(0xffffffffu, se, off);
        out[(n << 5) + t] = lg - mx - logf(se);
    }
}

// ---------------------------------------------------------------------------
// Launch
// ---------------------------------------------------------------------------
extern "C" void kernel_launch(void* const* d_in, const int* in_sizes, int n_in,
                              void* d_out, int out_size)
{
    const float* img  = (const float*)d_in[0];
    const float* qst  = (const float*)d_in[1];
    const float* cw0  = (const float*)d_in[2];
    const float* cw1  = (const float*)d_in[3];
    const float* cw2  = (const float*)d_in[4];
    const float* cw3  = (const float*)d_in[5];
    const float* bs0  = (const float*)d_in[6];
    const float* bb0  = (const float*)d_in[7];
    const float* bs1  = (const float*)d_in[8];
    const float* bb1  = (const float*)d_in[9];
    const float* bs2  = (const float*)d_in[10];
    const float* bb2  = (const float*)d_in[11];
    const float* bs3  = (const float*)d_in[12];
    const float* bb3  = (const float*)d_in[13];
    const float* gw1  = (const float*)d_in[14];
    const float* gb1  = (const float*)d_in[15];
    const float* gw2  = (const float*)d_in[16];
    const float* gb2  = (const float*)d_in[17];
    const float* gw3  = (const float*)d_in[18];
    const float* gb3  = (const float*)d_in[19];
    const float* gw4  = (const float*)d_in[20];
    const float* gb4  = (const float*)d_in[21];
    const float* fw1  = (const float*)d_in[22];
    const float* fb1  = (const float*)d_in[23];
    const float* fw2  = (const float*)d_in[24];
    const float* fb2  = (const float*)d_in[25];
    const float* clw  = (const float*)d_in[26];
    const float* clb  = (const float*)d_in[27];
    float* out = (float*)d_out;

    void* base_v = nullptr;
    cudaGetSymbolAddress(&base_v, g_scratch);
    float* base = (float*)base_v;
    float* c0 = base + C0_OFF;
    float* c1 = base + C1_OFF;
    float* c2 = base + C2_OFF;
    float* c3 = base + C3_OFF;
    float* hi = base + HI_OFF;
    float* hj = base + HJ_OFF;
    float* sp = base + SP_OFF;
    unsigned short* wp = (unsigned short*)(base + WP_OFF);

    cudaFuncSetAttribute(rn_g_mma, cudaFuncAttributeMaxDynamicSharedMemorySize, 79872);

    prep_w_kernel<<<768, 256>>>(gw2, gw3, gw4, wp);

    // conv0: 3->24, 128->64.  grid 64n x 64 slabs, 384 thr (CPT=4)
    conv_slab_kernel<3, 64, 1, 4><<<4096, 384>>>(img, cw0, bs0, bb0, c0, 128);
    // conv1: 24->24, 64->32.  grid 64n x 32 slabs, 384 thr (CPT=2)
    conv_slab_kernel<24, 32, 1, 2><<<2048, 384>>>(c0, cw1, bs1, bb1, c1, 64);
    // conv2: 24->24, 32->16.  grid 64n x 8 slabs (RPB=2), 384 thr
    conv_slab_kernel<24, 16, 2, 2><<<512, 384>>>(c1, cw2, bs2, bb2, c2, 32);
    // conv3: 24->24, 16->8.   grid 64n x 4 slabs (RPB=2), 192 thr
    conv_slab_kernel<24, 8, 2, 2><<<256, 192>>>(c2, cw3, bs3, bb3, c3, 16);

    g1_kernel<<<256, 256>>>(c3, qst, gw1, gb1, hi, hj);

    rn_g_mma<<<4096, 256, 79872>>>(hi, hj, wp, gb2, gb3, gb4, sp);

    f_kernel<<<64, 256>>>(sp, fw1, fb1, fw2, fb2, clw, clb, out);
}